// round 13
// baseline (speedup 1.0000x reference)
#include <cuda_runtime.h>
#include <cuda_bf16.h>
#include <math.h>
#include <stdint.h>

// ---------------------------------------------------------------------------
// MLA forward, all-bf16x3 tensor-core pipeline.
// R13 = R12 resubmission (R12 died on container acquisition, not code).
// gemm_bf3 inner-loop register-pressure fix (B-resident, A-frags streamed;
// peak live regs ~105 < 128 cap for 2 CTAs/SM) + split_w split into 3
// launches so ncu's captured launch #4 = gemm_bf3 (Kw=1024).
// ---------------------------------------------------------------------------

#define ROWS 4096
#define TDIM 2048
#define CDIM 2048
#define HNUM 16
#define DH   128
#define HD2  64

// ------------------------- scratch (device globals) ------------------------
__device__ float g_kr [ROWS * 1024];
__device__ float g_qr [ROWS * 1024];
__device__ float g_vl [ROWS * 2048];
__device__ uint32_t g_XH[ROWS * 1024],    g_XM[ROWS * 1024];
__device__ uint32_t g_WkvDH[512 * 1024],  g_WkvDM[512 * 1024];
__device__ uint32_t g_WqDH [512 * 1024],  g_WqDM [512 * 1024];
__device__ uint32_t g_WkUH [1024 * 256],  g_WkUM [1024 * 256];
__device__ uint32_t g_WvUH [2048 * 256],  g_WvUM [2048 * 256];
__device__ uint32_t g_WqUH [1024 * 256],  g_WqUM [1024 * 256];
__device__ uint32_t g_WrkH [1024 * 1024], g_WrkM [1024 * 1024];
__device__ uint32_t g_WrqH [1024 * 256],  g_WrqM [1024 * 256];
__device__ uint32_t g_WoH  [2048 * 1024], g_WoM  [2048 * 1024];
__device__ uint32_t g_kvdH[ROWS * 256],  g_kvdM[ROWS * 256];
__device__ uint32_t g_qdH [ROWS * 256],  g_qdM [ROWS * 256];
__device__ uint32_t g_QH[ROWS * 1024], g_QM[ROWS * 1024];
__device__ uint32_t g_KH[ROWS * 1024], g_KM[ROWS * 1024];
__device__ uint32_t g_VTH[2 * HNUM * 128 * 1024], g_VTM[2 * HNUM * 128 * 1024];
__device__ uint32_t g_attnH[ROWS * 1024], g_attnM[ROWS * 1024];

// =========================== helpers =======================================
__device__ __forceinline__ uint32_t smem_u32(const void* p) {
    uint32_t a;
    asm("{ .reg .u64 t; cvta.to.shared.u64 t, %1; cvt.u32.u64 %0, t; }"
        : "=r"(a) : "l"(p));
    return a;
}
__device__ __forceinline__ void cp16(uint32_t dst, const void* src) {
    asm volatile("cp.async.cg.shared.global [%0], [%1], 16;"
                 :: "r"(dst), "l"(src));
}
#define CP_COMMIT() asm volatile("cp.async.commit_group;" ::: "memory")
#define CP_WAIT(n)  asm volatile("cp.async.wait_group %0;" :: "n"(n) : "memory")

__device__ __forceinline__ void mma_bf16(float* d, const uint32_t* a,
                                         const uint32_t* b) {
    asm volatile(
        "mma.sync.aligned.m16n8k16.row.col.f32.bf16.bf16.f32 "
        "{%0,%1,%2,%3}, {%4,%5,%6,%7}, {%8,%9}, {%0,%1,%2,%3};"
        : "+f"(d[0]), "+f"(d[1]), "+f"(d[2]), "+f"(d[3])
        : "r"(a[0]), "r"(a[1]), "r"(a[2]), "r"(a[3]), "r"(b[0]), "r"(b[1]));
}
__device__ __forceinline__ void split_pack(float x0, float x1,
                                           uint32_t& wh, uint32_t& wm) {
    __nv_bfloat162 hh = __floats2bfloat162_rn(x0, x1);
    float f0 = __low2float(hh), f1 = __high2float(hh);
    __nv_bfloat162 mm = __floats2bfloat162_rn(x0 - f0, x1 - f1);
    wh = reinterpret_cast<uint32_t&>(hh);
    wm = reinterpret_cast<uint32_t&>(mm);
}
__device__ __forceinline__ float fexp(float x) {
    float t  = x * 1.4426950408889634f;
    float kf = rintf(t);
    float y  = (t - kf) * 0.6931471805599453f;
    float r  = fmaf(y, 1.3888888889e-3f, 8.3333333333e-3f);
    r = fmaf(y, r, 4.1666666667e-2f);
    r = fmaf(y, r, 1.6666666667e-1f);
    r = fmaf(y, r, 0.5f);
    r = fmaf(y, r, 1.0f);
    r = fmaf(y, r, 1.0f);
    int ki = (int)fmaxf(kf, -127.0f);
    return r * __int_as_float((ki + 127) << 23);
}

// ====================== split_w: fp32 -> bf16 hi/mid =======================
struct SJobs {
    const float* src[5];
    uint32_t* dh[5];
    uint32_t* dm[5];
    int end[5];
};
__global__ __launch_bounds__(256) void split_w(SJobs jb)
{
    int bx = blockIdx.x, seg = 0;
    while (bx >= jb.end[seg]) seg++;
    int start = seg ? jb.end[seg - 1] : 0;
    size_t i4 = (size_t)(bx - start) * 256 + threadIdx.x;
    float4 v = ((const float4*)jb.src[seg])[i4];
    uint32_t h0, m0, h1, m1;
    split_pack(v.x, v.y, h0, m0);
    split_pack(v.z, v.w, h1, m1);
    jb.dh[seg][i4 * 2] = h0;  jb.dh[seg][i4 * 2 + 1] = h1;
    jb.dm[seg][i4 * 2] = m0;  jb.dm[seg][i4 * 2 + 1] = m1;
}

// ====================== bf16x3 batch GEMM ==================================
#define GW 20
#define GARR (128 * GW)
#define GSTG (4 * GARR)
#define GEMM_SMEM (2 * GSTG * 4)  // 81920 B

#define OM_F32   0
#define OM_SPLIT 1
#define OM_QKMAP 2

struct GSeg {
    const uint32_t *aH, *aM, *bH, *bM;
    float* cF; uint32_t *cH, *cM;
    int ldF, ldW, mode, end;
};
struct GBatch { GSeg s[4]; };

__global__ __launch_bounds__(256, 2) void gemm_bf3(GBatch gb, int Kw)
{
    extern __shared__ uint32_t smw[];
    const uint32_t smb = smem_u32(smw);
    const int tid = threadIdx.x;
    const int wid = tid >> 5, lane = tid & 31;
    const int wm = wid >> 2, wn = wid & 3;
    const int g = lane >> 2, q = lane & 3;
    const int bm = blockIdx.y * 128;

    GSeg sg; int bn;
    {
        int bx = blockIdx.x;
        if (bx < gb.s[0].end)      { sg = gb.s[0]; bn = bx * 128; }
        else if (bx < gb.s[1].end) { sg = gb.s[1]; bn = (bx - gb.s[0].end) * 128; }
        else if (bx < gb.s[2].end) { sg = gb.s[2]; bn = (bx - gb.s[1].end) * 128; }
        else                       { sg = gb.s[3]; bn = (bx - gb.s[2].end) * 128; }
    }

    float c[4][4][4];
#pragma unroll
    for (int i = 0; i < 4; i++)
#pragma unroll
        for (int j = 0; j < 4; j++)
#pragma unroll
            for (int e = 0; e < 4; e++) c[i][j][e] = 0.f;

    const int KT = Kw / 16;

    auto issue = [&](int s, int k0w) {
#pragma unroll
        for (int j = 0; j < 8; j++) {
            int f = tid + j * 256;
            int arr = f >> 9, ff = f & 511;
            int row = ff >> 2, c4 = ff & 3;
            const uint32_t* src = (arr == 0) ? sg.aH : (arr == 1) ? sg.aM
                                : (arr == 2) ? sg.bH : sg.bM;
            int base = (arr < 2) ? bm : bn;
            uint32_t dst = smb + (uint32_t)(s * GSTG + arr * GARR
                                            + row * GW + c4 * 4) * 4;
            cp16(dst, src + (size_t)(base + row) * Kw + k0w + c4 * 4);
        }
    };

    issue(0, 0);
    CP_COMMIT();

    for (int it = 0; it < KT; it++) {
        if (it + 1 < KT) issue((it + 1) & 1, (it + 1) * 16);
        CP_COMMIT();
        CP_WAIT(1);
        __syncthreads();

        const uint32_t* Ah_s = smw + (it & 1) * GSTG;
        const uint32_t* Am_s = Ah_s + GARR;
        const uint32_t* Bh_s = Ah_s + 2 * GARR;
        const uint32_t* Bm_s = Ah_s + 3 * GARR;

#pragma unroll
        for (int ch = 0; ch < 2; ch++) {
            // B fragments resident (16 regs); A fragments streamed per i-tile
            uint32_t Bh[4][2], Bm[4][2];
#pragma unroll
            for (int j = 0; j < 4; j++) {
                int bw = (wn * 32 + j * 8 + g) * GW + ch * 8 + q;
                Bh[j][0] = Bh_s[bw]; Bh[j][1] = Bh_s[bw + 4];
                Bm[j][0] = Bm_s[bw]; Bm[j][1] = Bm_s[bw + 4];
            }
#pragma unroll
            for (int i = 0; i < 4; i++) {
                uint32_t Ah[4], Am[4];
                int aw = (wm * 64 + i * 16 + g) * GW + ch * 8 + q;
                Ah[0] = Ah_s[aw];              Am[0] = Am_s[aw];
                Ah[1] = Ah_s[aw + 8 * GW];     Am[1] = Am_s[aw + 8 * GW];
                Ah[2] = Ah_s[aw + 4];          Am[2] = Am_s[aw + 4];
                Ah[3] = Ah_s[aw + 8 * GW + 4]; Am[3] = Am_s[aw + 8 * GW + 4];
#pragma unroll
                for (int j = 0; j < 4; j++) {
                    mma_bf16(c[i][j], Ah, Bh[j]);
                    mma_bf16(c[i][j], Ah, Bm[j]);
                    mma_bf16(c[i][j], Am, Bh[j]);
                }
            }
        }
        __syncthreads();
    }

    if (sg.mode == OM_F32) {
#pragma unroll
        for (int i = 0; i < 4; i++)
#pragma unroll
            for (int j = 0; j < 4; j++) {
                int row0 = bm + wm * 64 + i * 16 + g;
                int col  = bn + wn * 32 + j * 8 + 2 * q;
                *(float2*)&sg.cF[(size_t)row0 * sg.ldF + col] =
                    make_float2(c[i][j][0], c[i][j][1]);
                *(float2*)&sg.cF[(size_t)(row0 + 8) * sg.ldF + col] =
                    make_float2(c[i][j][2], c[i][j][3]);
            }
    } else {
        const int bnw = bn >> 1;
#pragma unroll
        for (int i = 0; i < 4; i++)
#pragma unroll
            for (int j = 0; j < 4; j++) {
                int row0 = bm + wm * 64 + i * 16 + g;
                uint32_t ww = bnw + wn * 16 + j * 4 + q;
                uint32_t ow = (sg.mode == OM_QKMAP) ? (ww + (ww & ~31u)) : ww;
                uint32_t hw, mw;
                split_pack(c[i][j][0], c[i][j][1], hw, mw);
                sg.cH[(size_t)row0 * sg.ldW + ow] = hw;
                sg.cM[(size_t)row0 * sg.ldW + ow] = mw;
                split_pack(c[i][j][2], c[i][j][3], hw, mw);
                sg.cH[(size_t)(row0 + 8) * sg.ldW + ow] = hw;
                sg.cM[(size_t)(row0 + 8) * sg.ldW + ow] = mw;
            }
    }
}

// ============ split_vr: V transpose+split, rope-split of kr/qr =============
__global__ __launch_bounds__(256) void split_vr(
    const float* __restrict__ vl,
    const float* __restrict__ kr, const float* __restrict__ qr,
    uint32_t* __restrict__ VTH, uint32_t* __restrict__ VTM,
    uint32_t* __restrict__ QH, uint32_t* __restrict__ QM,
    uint32_t* __restrict__ KH, uint32_t* __restrict__ KM)
{
    __shared__ float smT[128 * 66];
    const int bx = blockIdx.x, tid = threadIdx.x;
    if (bx < 1024) {
        const int pt = bx & 31, h = (bx >> 5) & 15, b = bx >> 9;
        const int t0 = pt * 64;
        for (int i = tid; i < 64 * 128; i += 256) {
            int row = i >> 7, col = i & 127;
            smT[col * 66 + row] =
                vl[(size_t)(b * TDIM + t0 + row) * 2048 + h * DH + col];
        }
        __syncthreads();
        const int lane = tid & 31, w = tid >> 5;
#pragma unroll
        for (int pass = 0; pass < 16; pass++) {
            int d = pass * 8 + w;
            float2 v = *(float2*)&smT[d * 66 + 2 * lane];
            uint32_t hw, mw; split_pack(v.x, v.y, hw, mw);
            size_t o = ((size_t)(b * HNUM + h) * 128 + d) * 1024 + pt * 32 + lane;
            VTH[o] = hw; VTM[o] = mw;
        }
    } else {
        const int rid = bx - 1024;
        const int tens = rid >> 11;
        const int baserow = (rid & 2047) * 2;
        const float* src = tens ? qr : kr;
        uint32_t* OH = tens ? QH : KH;
        uint32_t* OM = tens ? QM : KM;
#pragma unroll
        for (int j = 0; j < 4; j++) {
            int u = tid + j * 256;
            int row = baserow + (u >> 9);
            int w = u & 511;
            int h = w >> 5, u5 = w & 31;
            float2 v = *(const float2*)&src[(size_t)row * 1024 + h * HD2 + 2 * u5];
            int t = row & (TDIM - 1);
            int pr = h * 32 + u5;
            const float c1 = (float)(-9.210340371976184 / 1024.0);
            float fr  = expf((float)(2 * pr) * c1);
            float ang = (float)t * fr;
            double ad = (double)ang;
            double rr = ad - floor(ad * 0.15915494309189535) * 6.283185307179586;
            float s = sinf((float)rr), cc = cosf((float)rr);
            float xe = v.x, xo = v.y;
            float r0 = xe * cc - xo * s;
            float r1 = xo * cc + xe * s;
            uint32_t hw, mw; split_pack(r0, r1, hw, mw);
            OH[(size_t)row * 1024 + h * 64 + 32 + u5] = hw;
            OM[(size_t)row * 1024 + h * 64 + 32 + u5] = mw;
        }
    }
}

// ====================== bf16x3 flash attention =============================
#define AQH 0
#define AQM 4352
#define AKH 8704
#define AKM 13056
#define AVH 17408
#define AVM 19968
#define APH 22528
#define APM 23808
#define ATTN_SMEM (25088 * 4)

__global__ __launch_bounds__(128) void attn_bf3(
    const uint32_t* __restrict__ QHg, const uint32_t* __restrict__ QMg,
    const uint32_t* __restrict__ KHg, const uint32_t* __restrict__ KMg,
    const uint32_t* __restrict__ VTHg, const uint32_t* __restrict__ VTMg,
    uint32_t* __restrict__ OHg, uint32_t* __restrict__ OMg)
{
    extern __shared__ uint32_t smw[];
    const uint32_t smb = smem_u32(smw);
    const int tid = threadIdx.x, wid = tid >> 5, lane = tid & 31;
    const int g = lane >> 2, q = lane & 3;
    const int it = 31 - blockIdx.x;
    const int h = blockIdx.y, b = blockIdx.z;
    const int q0 = it * 64, rowbase = b * TDIM;
    const float scale = 0.08838834764831845f;

    uint32_t* QH = smw + AQH;  uint32_t* QM = smw + AQM;
    uint32_t* VH = smw + AVH;  uint32_t* VM = smw + AVM;
    uint32_t* PH = smw + APH;  uint32_t* PM = smw + APM;

    auto cpK = [&](int tk, int slot) {
#pragma unroll
        for (int j = 0; j < 8; j++) {
            int f = tid + j * 128;
            int ff = f & 511;
            int row = ff >> 4, c4 = ff & 15;
            const uint32_t* gsrc = (f < 512) ? KHg : KMg;
            uint32_t dst = smb + (((f < 512) ? AKH : AKM) + slot * 2176
                                  + row * 68 + c4 * 4) * 4;
            cp16(dst, gsrc + (size_t)(rowbase + tk + row) * 1024 + h * 64 + c4 * 4);
        }
    };
    auto cpV = [&](int tk) {
#pragma unroll
        for (int j = 0; j < 8; j++) {
            int f = tid + j * 128;
            int ff = f & 511;
            int d = ff >> 2, c4 = ff & 3;
            const uint32_t* gsrc = (f < 512) ? VTHg : VTMg;
            uint32_t dst = smb + (((f < 512) ? AVH : AVM) + d * 20 + c4 * 4) * 4;
            cp16(dst, gsrc + ((size_t)(b * HNUM + h) * 128 + d) * 1024
                        + (tk >> 1) + c4 * 4);
        }
    };

#pragma unroll
    for (int j = 0; j < 16; j++) {
        int f = tid + j * 128;
        int ff = f & 1023;
        int row = ff >> 4, c4 = ff & 15;
        const uint32_t* gsrc = (f < 1024) ? QHg : QMg;
        uint32_t dst = smb + (((f < 1024) ? AQH : AQM) + row * 68 + c4 * 4) * 4;
        cp16(dst, gsrc + (size_t)(rowbase + q0 + row) * 1024 + h * 64 + c4 * 4);
    }
    cpK(0, 0);
    CP_COMMIT();
    cpV(0);
    CP_COMMIT();

    float o[16][4];
#pragma unroll
    for (int jt = 0; jt < 16; jt++)
#pragma unroll
        for (int e = 0; e < 4; e++) o[jt][e] = 0.f;
    float m_old0 = -1e30f, m_old1 = -1e30f, l0 = 0.f, l1 = 0.f;

    const int kmax = 2 * it + 1;
    const int gr0 = q0 + 16 * wid + g, gr1 = gr0 + 8;
    const int qwr = 16 * wid;

    for (int kb = 0; kb <= kmax; kb++) {
        if (kb < kmax) cpK((kb + 1) * 32, (kb + 1) & 1);
        CP_COMMIT();
        CP_WAIT(2);
        __syncthreads();

        const bool active = (kb * 32 <= q0 + qwr + 15);
        if (active) {
            const uint32_t* KHs = smw + AKH + (kb & 1) * 2176;
            const uint32_t* KMs = smw + AKM + (kb & 1) * 2176;

            float sacc[4][4];
#pragma unroll
            for (int j = 0; j < 4; j++)
#pragma unroll
                for (int e = 0; e < 4; e++) sacc[j][e] = 0.f;

#pragma unroll
            for (int c = 0; c < 8; c++) {
                uint32_t Ah[4], Am[4];
                int aw = (qwr + g) * 68 + c * 8 + q;
                Ah[0] = QH[aw];              Am[0] = QM[aw];
                Ah[1] = QH[aw + 8 * 68];     Am[1] = QM[aw + 8 * 68];
                Ah[2] = QH[aw + 4];          Am[2] = QM[aw + 4];
                Ah[3] = QH[aw + 8 * 68 + 4]; Am[3] = QM[aw + 8 * 68 + 4];
#pragma unroll
                for (int j = 0; j < 4; j++) {
                    uint32_t Bh[2], Bm[2];
                    int bw = (j * 8 + g) * 68 + c * 8 + q;
                    Bh[0] = KHs[bw]; Bh[1] = KHs[bw + 4];
                    Bm[0] = KMs[bw]; Bm[1] = KMs[bw + 4];
                    mma_bf16(sacc[j], Ah, Bh);
                    mma_bf16(sacc[j], Ah, Bm);
                    mma_bf16(sacc[j], Am, Bh);
                }
            }

            float mx0 = -1e30f, mx1 = -1e30f;
#pragma unroll
            for (int j = 0; j < 4; j++) {
                int colb = kb * 32 + j * 8 + 2 * q;
                float v0 = sacc[j][0] * scale; if (colb     > gr0) v0 = -1e30f;
                float v1 = sacc[j][1] * scale; if (colb + 1 > gr0) v1 = -1e30f;
                float v2 = sacc[j][2] * scale; if (colb     > gr1) v2 = -1e30f;
                float v3 = sacc[j][3] * scale; if (colb + 1 > gr1) v3 = -1e30f;
                sacc[j][0] = v0; sacc[j][1] = v1; sacc[j][2] = v2; sacc[j][3] = v3;
                mx0 = fmaxf(mx0, fmaxf(v0, v1));
                mx1 = fmaxf(mx1, fmaxf(v2, v3));
            }
            mx0 = fmaxf(mx0, __shfl_xor_sync(0xffffffffu, mx0, 1));
            mx0 = fmaxf(mx0, __shfl_xor_sync(0xffffffffu, mx0, 2));
            mx1 = fmaxf(mx1, __shfl_xor_sync(0xffffffffu, mx1, 1));
            mx1 = fmaxf(mx1, __shfl_xor_sync(0xffffffffu, mx1, 2));

            float mn0 = fmaxf(m_old0, mx0), mn1 = fmaxf(m_old1, mx1);
            float al0 = fexp(m_old0 - mn0), al1 = fexp(m_old1 - mn1);
            float ps0 = 0.f, ps1 = 0.f;
#pragma unroll
            for (int j = 0; j < 4; j++) {
                float p0 = fexp(sacc[j][0] - mn0);
                float p1 = fexp(sacc[j][1] - mn0);
                float p2 = fexp(sacc[j][2] - mn1);
                float p3 = fexp(sacc[j][3] - mn1);
                ps0 += p0 + p1; ps1 += p2 + p3;
                uint32_t hw, mw;
                split_pack(p0, p1, hw, mw);
                PH[(qwr + g) * 20 + j * 4 + q] = hw;
                PM[(qwr + g) * 20 + j * 4 + q] = mw;
                split_pack(p2, p3, hw, mw);
                PH[(qwr + g + 8) * 20 + j * 4 + q] = hw;
                PM[(qwr + g + 8) * 20 + j * 4 + q] = mw;
            }
            ps0 += __shfl_xor_sync(0xffffffffu, ps0, 1);
            ps0 += __shfl_xor_sync(0xffffffffu, ps0, 2);
            ps1 += __shfl_xor_sync(0xffffffffu, ps1, 1);
            ps1 += __shfl_xor_sync(0xffffffffu, ps1, 2);
            l0 = l0 * al0 + ps0; l1 = l1 * al1 + ps1;
            m_old0 = mn0; m_old1 = mn1;
#pragma unroll
            for (int jt = 0; jt < 16; jt++) {
                o[jt][0] *= al0; o[jt][1] *= al0;
                o[jt][2] *= al1; o[jt][3] *= al1;
            }
        }

        CP_WAIT(1);
        __syncthreads();

        if (active) {
            __syncwarp();
#pragma unroll
            for (int c = 0; c < 2; c++) {
                uint32_t Ah[4], Am[4];
                int aw = (qwr + g) * 20 + c * 8 + q;
                Ah[0] = PH[aw];              Am[0] = PM[aw];
                Ah[1] = PH[aw + 8 * 20];     Am[1] = PM[aw + 8 * 20];
                Ah[2] = PH[aw + 4];          Am[2] = PM[aw + 4];
                Ah[3] = PH[aw + 8 * 20 + 4]; Am[3] = PM[aw + 8 * 20 + 4];
#pragma unroll
                for (int jt = 0; jt < 16; jt++) {
                    uint32_t Bh[2], Bm[2];
                    int bw = (jt * 8 + g) * 20 + c * 8 + q;
                    Bh[0] = VH[bw]; Bh[1] = VH[bw + 4];
                    Bm[0] = VM[bw]; Bm[1] = VM[bw + 4];
                    mma_bf16(o[jt], Ah, Bh);
                    mma_bf16(o[jt], Ah, Bm);
                    mma_bf16(o[jt], Am, Bh);
                }
            }
        }

        __syncthreads();
        if (kb < kmax) cpV((kb + 1) * 32);
        CP_COMMIT();
    }

    float inv0 = 1.f / l0, inv1 = 1.f / l1;
    size_t ob0 = (size_t)(rowbase + gr0) * 1024 + h * 64;
    size_t ob1 = (size_t)(rowbase + gr1) * 1024 + h * 64;
#pragma unroll
    for (int jt = 0; jt < 16; jt++) {
        uint32_t hw, mw;
        split_pack(o[jt][0] * inv0, o[jt][1] * inv0, hw, mw);
        OHg[ob0 + jt * 4 + q] = hw;
        OMg[ob0 + jt * 4 + q] = mw;
        split_pack(o[jt][2] * inv1, o[jt][3] * inv1, hw, mw);
        OHg[ob1 + jt * 4 + q] = hw;
        OMg[ob1 + jt * 4 + q] = mw;
    }
}

// ------------------------------- launch ------------------------------------
extern "C" void kernel_launch(void* const* d_in, const int* in_sizes, int n_in,
                              void* d_out, int out_size)
{
    (void)in_sizes; (void)n_in; (void)out_size;
    const float* x    = (const float*)d_in[0];
    const float* WkvD = (const float*)d_in[1];
    const float* WqD  = (const float*)d_in[2];
    const float* WkU  = (const float*)d_in[3];
    const float* WvU  = (const float*)d_in[4];
    const float* WqU  = (const float*)d_in[5];
    const float* Wrk  = (const float*)d_in[6];
    const float* Wrq  = (const float*)d_in[7];
    const float* Wo   = (const float*)d_in[8];
    float* out = (float*)d_out;

    float *kr, *qr, *vl;
    uint32_t *XH, *XM, *WkvDH, *WkvDM, *WqDH, *WqDM, *WkUH, *WkUM;
    uint32_t *WvUH, *WvUM, *WqUH, *WqUM, *WrkH, *WrkM, *WrqH, *WrqM;
    uint32_t *WoH, *WoM, *kvdH, *kvdM, *qdH, *qdM;
    uint32_t *QH, *QM, *KH, *KM, *VTH, *VTM, *attnH, *attnM;
    cudaGetSymbolAddress((void**)&kr,   g_kr);
    cudaGetSymbolAddress((void**)&qr,   g_qr);
    cudaGetSymbolAddress((void**)&vl,   g_vl);
    cudaGetSymbolAddress((void**)&XH,   g_XH);    cudaGetSymbolAddress((void**)&XM,   g_XM);
    cudaGetSymbolAddress((void**)&WkvDH,g_WkvDH); cudaGetSymbolAddress((void**)&WkvDM,g_WkvDM);
    cudaGetSymbolAddress((void**)&WqDH, g_WqDH);  cudaGetSymbolAddress((void**)&WqDM, g_WqDM);
    cudaGetSymbolAddress((void**)&WkUH, g_WkUH);  cudaGetSymbolAddress((void**)&WkUM, g_WkUM);
    cudaGetSymbolAddress((void**)&WvUH, g_WvUH);  cudaGetSymbolAddress((void**)&WvUM, g_WvUM);
    cudaGetSymbolAddress((void**)&WqUH, g_WqUH);  cudaGetSymbolAddress((void**)&WqUM, g_WqUM);
    cudaGetSymbolAddress((void**)&WrkH, g_WrkH);  cudaGetSymbolAddress((void**)&WrkM, g_WrkM);
    cudaGetSymbolAddress((void**)&WrqH, g_WrqH);  cudaGetSymbolAddress((void**)&WrqM, g_WrqM);
    cudaGetSymbolAddress((void**)&WoH,  g_WoH);   cudaGetSymbolAddress((void**)&WoM,  g_WoM);
    cudaGetSymbolAddress((void**)&kvdH, g_kvdH);  cudaGetSymbolAddress((void**)&kvdM, g_kvdM);
    cudaGetSymbolAddress((void**)&qdH,  g_qdH);   cudaGetSymbolAddress((void**)&qdM,  g_qdM);
    cudaGetSymbolAddress((void**)&QH,   g_QH);    cudaGetSymbolAddress((void**)&QM,   g_QM);
    cudaGetSymbolAddress((void**)&KH,   g_KH);    cudaGetSymbolAddress((void**)&KM,   g_KM);
    cudaGetSymbolAddress((void**)&VTH,  g_VTH);   cudaGetSymbolAddress((void**)&VTM,  g_VTM);
    cudaGetSymbolAddress((void**)&attnH,g_attnH); cudaGetSymbolAddress((void**)&attnM,g_attnM);

    cudaFuncSetAttribute(gemm_bf3, cudaFuncAttributeMaxDynamicSharedMemorySize,
                         GEMM_SMEM);
    cudaFuncSetAttribute(attn_bf3, cudaFuncAttributeMaxDynamicSharedMemorySize,
                         ATTN_SMEM);

    // L1: split x   (8192 blocks)
    {
        SJobs jb{};
        jb.src[0] = x; jb.dh[0] = XH; jb.dm[0] = XM;
        for (int i = 0; i < 5; i++) jb.end[i] = 8192;
        split_w<<<8192, 256>>>(jb);
    }
    // L2: split up-weights {WkvD, WqD, WkU, WvU, WqU}  (4096 blocks)
    {
        SJobs jb{};
        jb.src[0] = WkvD; jb.dh[0] = WkvDH; jb.dm[0] = WkvDM;
        jb.src[1] = WqD;  jb.dh[1] = WqDH;  jb.dm[1] = WqDM;
        jb.src[2] = WkU;  jb.dh[2] = WkUH;  jb.dm[2] = WkUM;
        jb.src[3] = WvU;  jb.dh[3] = WvUH;  jb.dm[3] = WvUM;
        jb.src[4] = WqU;  jb.dh[4] = WqUH;  jb.dm[4] = WqUM;
        int cnt[5] = {1024, 1024, 512, 1024, 512};
        int e = 0;
        for (int i = 0; i < 5; i++) { e += cnt[i]; jb.end[i] = e; }
        split_w<<<e, 256>>>(jb);
    }
    // L3: split big weights {Wrk, Wrq, Wo}  (6656 blocks)
    {
        SJobs jb{};
        jb.src[0] = Wrk; jb.dh[0] = WrkH; jb.dm[0] = WrkM;
        jb.src[1] = Wrq; jb.dh[1] = WrqH; jb.dm[1] = WrqM;
        jb.src[2] = Wo;  jb.dh[2] = WoH;  jb.dm[2] = WoM;
        int cnt[3] = {2048, 512, 4096};
        int e = 0;
        for (int i = 0; i < 3; i++) { e += cnt[i]; jb.end[i] = e; }
        jb.end[3] = e; jb.end[4] = e;
        split_w<<<e, 256>>>(jb);
    }
    // L4 (ncu-captured): x -> {kvd, qd, kr}   Kw=1024
    {
        GBatch gb;
        gb.s[0] = { XH, XM, WkvDH, WkvDM, nullptr, kvdH, kvdM, 0, 256, OM_SPLIT, 4 };
        gb.s[1] = { XH, XM, WqDH,  WqDM,  nullptr, qdH,  qdM,  0, 256, OM_SPLIT, 8 };
        gb.s[2] = { XH, XM, WrkH,  WrkM,  kr, nullptr, nullptr, 1024, 0, OM_F32, 16 };
        gb.s[3] = gb.s[2];
        gemm_bf3<<<dim3(16, 32), 256, GEMM_SMEM>>>(gb, 1024);
    }
    // L5: {kvd,qd} -> {kc->K, qc->Q, vl, qr}  Kw=256
    {
        GBatch gb;
        gb.s[0] = { kvdH, kvdM, WkUH, WkUM, nullptr, KH, KM, 0, 1024, OM_QKMAP, 8 };
        gb.s[1] = { qdH,  qdM,  WqUH, WqUM, nullptr, QH, QM, 0, 1024, OM_QKMAP, 16 };
        gb.s[2] = { kvdH, kvdM, WvUH, WvUM, vl, nullptr, nullptr, 2048, 0, OM_F32, 32 };
        gb.s[3] = { qdH,  qdM,  WrqH, WrqM, qr, nullptr, nullptr, 1024, 0, OM_F32, 40 };
        gemm_bf3<<<dim3(40, 32), 256, GEMM_SMEM>>>(gb, 256);
    }
    // L6: V transpose+split, rope+split
    split_vr<<<5120, 256>>>(vl, kr, qr, VTH, VTM, QH, QM, KH, KM);
    // L7: attention
    attn_bf3<<<dim3(32, HNUM, 2), 128, ATTN_SMEM>>>(
        QH, QM, KH, KM, VTH, VTM, attnH, attnM);
    // L8: output projection  Kw=1024
    {
        GBatch gb;
        gb.s[0] = { attnH, attnM, WoH, WoM, out, nullptr, nullptr, 2048, 0, OM_F32, 16 };
        gb.s[1] = gb.s[0]; gb.s[2] = gb.s[0]; gb.s[3] = gb.s[0];
        gemm_bf3<<<dim3(16, 32), 256, GEMM_SMEM>>>(gb, 1024);
    }
}

// round 15
// speedup vs baseline: 1.0585x; 1.0585x over previous
#include <cuda_runtime.h>
#include <cuda_bf16.h>
#include <math.h>
#include <stdint.h>

// ---------------------------------------------------------------------------
// MLA forward, all-bf16x3 tensor-core pipeline.
// R15 = R14 resubmission (R14 died on container acquisition, not code).
// ldmatrix fragment loads in gemm_bf3 and attn_bf3 (96 LDS.32/iter ->
// 24 LDSM.x4; attacks the issue/latency bound: tensor=50.3%, issue=21.2%).
// ---------------------------------------------------------------------------

#define ROWS 4096
#define TDIM 2048
#define CDIM 2048
#define HNUM 16
#define DH   128
#define HD2  64

// ------------------------- scratch (device globals) ------------------------
__device__ float g_kr [ROWS * 1024];
__device__ float g_qr [ROWS * 1024];
__device__ float g_vl [ROWS * 2048];
__device__ uint32_t g_XH[ROWS * 1024],    g_XM[ROWS * 1024];
__device__ uint32_t g_WkvDH[512 * 1024],  g_WkvDM[512 * 1024];
__device__ uint32_t g_WqDH [512 * 1024],  g_WqDM [512 * 1024];
__device__ uint32_t g_WkUH [1024 * 256],  g_WkUM [1024 * 256];
__device__ uint32_t g_WvUH [2048 * 256],  g_WvUM [2048 * 256];
__device__ uint32_t g_WqUH [1024 * 256],  g_WqUM [1024 * 256];
__device__ uint32_t g_WrkH [1024 * 1024], g_WrkM [1024 * 1024];
__device__ uint32_t g_WrqH [1024 * 256],  g_WrqM [1024 * 256];
__device__ uint32_t g_WoH  [2048 * 1024], g_WoM  [2048 * 1024];
__device__ uint32_t g_kvdH[ROWS * 256],  g_kvdM[ROWS * 256];
__device__ uint32_t g_qdH [ROWS * 256],  g_qdM [ROWS * 256];
__device__ uint32_t g_QH[ROWS * 1024], g_QM[ROWS * 1024];
__device__ uint32_t g_KH[ROWS * 1024], g_KM[ROWS * 1024];
__device__ uint32_t g_VTH[2 * HNUM * 128 * 1024], g_VTM[2 * HNUM * 128 * 1024];
__device__ uint32_t g_attnH[ROWS * 1024], g_attnM[ROWS * 1024];

// =========================== helpers =======================================
__device__ __forceinline__ uint32_t smem_u32(const void* p) {
    uint32_t a;
    asm("{ .reg .u64 t; cvta.to.shared.u64 t, %1; cvt.u32.u64 %0, t; }"
        : "=r"(a) : "l"(p));
    return a;
}
__device__ __forceinline__ void cp16(uint32_t dst, const void* src) {
    asm volatile("cp.async.cg.shared.global [%0], [%1], 16;"
                 :: "r"(dst), "l"(src));
}
#define CP_COMMIT() asm volatile("cp.async.commit_group;" ::: "memory")
#define CP_WAIT(n)  asm volatile("cp.async.wait_group %0;" :: "n"(n) : "memory")

__device__ __forceinline__ void mma_bf16(float* d, const uint32_t* a,
                                         const uint32_t* b) {
    asm volatile(
        "mma.sync.aligned.m16n8k16.row.col.f32.bf16.bf16.f32 "
        "{%0,%1,%2,%3}, {%4,%5,%6,%7}, {%8,%9}, {%0,%1,%2,%3};"
        : "+f"(d[0]), "+f"(d[1]), "+f"(d[2]), "+f"(d[3])
        : "r"(a[0]), "r"(a[1]), "r"(a[2]), "r"(a[3]), "r"(b[0]), "r"(b[1]));
}
__device__ __forceinline__ void ldsm_x4(uint32_t& r0, uint32_t& r1,
                                        uint32_t& r2, uint32_t& r3,
                                        uint32_t addr) {
    asm volatile("ldmatrix.sync.aligned.m8n8.x4.shared.b16 {%0,%1,%2,%3}, [%4];"
                 : "=r"(r0), "=r"(r1), "=r"(r2), "=r"(r3) : "r"(addr));
}
__device__ __forceinline__ void split_pack(float x0, float x1,
                                           uint32_t& wh, uint32_t& wm) {
    __nv_bfloat162 hh = __floats2bfloat162_rn(x0, x1);
    float f0 = __low2float(hh), f1 = __high2float(hh);
    __nv_bfloat162 mm = __floats2bfloat162_rn(x0 - f0, x1 - f1);
    wh = reinterpret_cast<uint32_t&>(hh);
    wm = reinterpret_cast<uint32_t&>(mm);
}
__device__ __forceinline__ float fexp(float x) {
    float t  = x * 1.4426950408889634f;
    float kf = rintf(t);
    float y  = (t - kf) * 0.6931471805599453f;
    float r  = fmaf(y, 1.3888888889e-3f, 8.3333333333e-3f);
    r = fmaf(y, r, 4.1666666667e-2f);
    r = fmaf(y, r, 1.6666666667e-1f);
    r = fmaf(y, r, 0.5f);
    r = fmaf(y, r, 1.0f);
    r = fmaf(y, r, 1.0f);
    int ki = (int)fmaxf(kf, -127.0f);
    return r * __int_as_float((ki + 127) << 23);
}

// ====================== split_w: fp32 -> bf16 hi/mid =======================
struct SJobs {
    const float* src[5];
    uint32_t* dh[5];
    uint32_t* dm[5];
    int end[5];
};
__global__ __launch_bounds__(256) void split_w(SJobs jb)
{
    int bx = blockIdx.x, seg = 0;
    while (bx >= jb.end[seg]) seg++;
    int start = seg ? jb.end[seg - 1] : 0;
    size_t i4 = (size_t)(bx - start) * 256 + threadIdx.x;
    float4 v = ((const float4*)jb.src[seg])[i4];
    uint32_t h0, m0, h1, m1;
    split_pack(v.x, v.y, h0, m0);
    split_pack(v.z, v.w, h1, m1);
    jb.dh[seg][i4 * 2] = h0;  jb.dh[seg][i4 * 2 + 1] = h1;
    jb.dm[seg][i4 * 2] = m0;  jb.dm[seg][i4 * 2 + 1] = m1;
}

// ====================== bf16x3 batch GEMM ==================================
#define GW 20
#define GARR (128 * GW)
#define GSTG (4 * GARR)
#define GEMM_SMEM (2 * GSTG * 4)  // 81920 B

#define OM_F32   0
#define OM_SPLIT 1
#define OM_QKMAP 2

struct GSeg {
    const uint32_t *aH, *aM, *bH, *bM;
    float* cF; uint32_t *cH, *cM;
    int ldF, ldW, mode, end;
};
struct GBatch { GSeg s[4]; };

__global__ __launch_bounds__(256, 2) void gemm_bf3(GBatch gb, int Kw)
{
    extern __shared__ uint32_t smw[];
    const uint32_t smb = smem_u32(smw);
    const int tid = threadIdx.x;
    const int wid = tid >> 5, lane = tid & 31;
    const int wm = wid >> 2, wn = wid & 3;
    const int g = lane >> 2, q = lane & 3;
    const int r8 = lane & 7, mq = lane >> 3;
    const int bm = blockIdx.y * 128;

    GSeg sg; int bn;
    {
        int bx = blockIdx.x;
        if (bx < gb.s[0].end)      { sg = gb.s[0]; bn = bx * 128; }
        else if (bx < gb.s[1].end) { sg = gb.s[1]; bn = (bx - gb.s[0].end) * 128; }
        else if (bx < gb.s[2].end) { sg = gb.s[2]; bn = (bx - gb.s[1].end) * 128; }
        else                       { sg = gb.s[3]; bn = (bx - gb.s[2].end) * 128; }
    }

    float c[4][4][4];
#pragma unroll
    for (int i = 0; i < 4; i++)
#pragma unroll
        for (int j = 0; j < 4; j++)
#pragma unroll
            for (int e = 0; e < 4; e++) c[i][j][e] = 0.f;

    const int KT = Kw / 16;

    auto issue = [&](int s, int k0w) {
#pragma unroll
        for (int j = 0; j < 8; j++) {
            int f = tid + j * 256;
            int arr = f >> 9, ff = f & 511;
            int row = ff >> 2, c4 = ff & 3;
            const uint32_t* src = (arr == 0) ? sg.aH : (arr == 1) ? sg.aM
                                : (arr == 2) ? sg.bH : sg.bM;
            int base = (arr < 2) ? bm : bn;
            uint32_t dst = smb + (uint32_t)(s * GSTG + arr * GARR
                                            + row * GW + c4 * 4) * 4;
            cp16(dst, src + (size_t)(base + row) * Kw + k0w + c4 * 4);
        }
    };

    issue(0, 0);
    CP_COMMIT();

    for (int it = 0; it < KT; it++) {
        if (it + 1 < KT) issue((it + 1) & 1, (it + 1) * 16);
        CP_COMMIT();
        CP_WAIT(1);
        __syncthreads();

        const uint32_t sA_h = smb + (uint32_t)((it & 1) * GSTG) * 4;
        const uint32_t sA_m = sA_h + GARR * 4;
        const uint32_t sB_h = sA_h + 2 * GARR * 4;
        const uint32_t sB_m = sA_h + 3 * GARR * 4;

#pragma unroll
        for (int ch = 0; ch < 2; ch++) {
            // B fragments via ldmatrix.x4: one call covers a j-pair
            uint32_t Bh[4][2], Bm[4][2];
#pragma unroll
            for (int u = 0; u < 2; u++) {
                uint32_t woff = (uint32_t)(((wn * 32 + (2 * u + (mq >> 1)) * 8 + r8) * GW
                                            + ch * 8 + (mq & 1) * 4) * 4);
                ldsm_x4(Bh[2*u][0], Bh[2*u][1], Bh[2*u+1][0], Bh[2*u+1][1], sB_h + woff);
                ldsm_x4(Bm[2*u][0], Bm[2*u][1], Bm[2*u+1][0], Bm[2*u+1][1], sB_m + woff);
            }
#pragma unroll
            for (int i = 0; i < 4; i++) {
                uint32_t Ah[4], Am[4];
                uint32_t woff = (uint32_t)(((wm * 64 + i * 16 + r8 + (mq & 1) * 8) * GW
                                            + ch * 8 + (mq >> 1) * 4) * 4);
                ldsm_x4(Ah[0], Ah[1], Ah[2], Ah[3], sA_h + woff);
                ldsm_x4(Am[0], Am[1], Am[2], Am[3], sA_m + woff);
#pragma unroll
                for (int j = 0; j < 4; j++) {
                    mma_bf16(c[i][j], Ah, Bh[j]);
                    mma_bf16(c[i][j], Ah, Bm[j]);
                    mma_bf16(c[i][j], Am, Bh[j]);
                }
            }
        }
        __syncthreads();
    }

    if (sg.mode == OM_F32) {
#pragma unroll
        for (int i = 0; i < 4; i++)
#pragma unroll
            for (int j = 0; j < 4; j++) {
                int row0 = bm + wm * 64 + i * 16 + g;
                int col  = bn + wn * 32 + j * 8 + 2 * q;
                *(float2*)&sg.cF[(size_t)row0 * sg.ldF + col] =
                    make_float2(c[i][j][0], c[i][j][1]);
                *(float2*)&sg.cF[(size_t)(row0 + 8) * sg.ldF + col] =
                    make_float2(c[i][j][2], c[i][j][3]);
            }
    } else {
        const int bnw = bn >> 1;
#pragma unroll
        for (int i = 0; i < 4; i++)
#pragma unroll
            for (int j = 0; j < 4; j++) {
                int row0 = bm + wm * 64 + i * 16 + g;
                uint32_t ww = bnw + wn * 16 + j * 4 + q;
                uint32_t ow = (sg.mode == OM_QKMAP) ? (ww + (ww & ~31u)) : ww;
                uint32_t hw, mw;
                split_pack(c[i][j][0], c[i][j][1], hw, mw);
                sg.cH[(size_t)row0 * sg.ldW + ow] = hw;
                sg.cM[(size_t)row0 * sg.ldW + ow] = mw;
                split_pack(c[i][j][2], c[i][j][3], hw, mw);
                sg.cH[(size_t)(row0 + 8) * sg.ldW + ow] = hw;
                sg.cM[(size_t)(row0 + 8) * sg.ldW + ow] = mw;
            }
    }
}

// ============ split_vr: V transpose+split, rope-split of kr/qr =============
__global__ __launch_bounds__(256) void split_vr(
    const float* __restrict__ vl,
    const float* __restrict__ kr, const float* __restrict__ qr,
    uint32_t* __restrict__ VTH, uint32_t* __restrict__ VTM,
    uint32_t* __restrict__ QH, uint32_t* __restrict__ QM,
    uint32_t* __restrict__ KH, uint32_t* __restrict__ KM)
{
    __shared__ float smT[128 * 66];
    const int bx = blockIdx.x, tid = threadIdx.x;
    if (bx < 1024) {
        const int pt = bx & 31, h = (bx >> 5) & 15, b = bx >> 9;
        const int t0 = pt * 64;
        for (int i = tid; i < 64 * 128; i += 256) {
            int row = i >> 7, col = i & 127;
            smT[col * 66 + row] =
                vl[(size_t)(b * TDIM + t0 + row) * 2048 + h * DH + col];
        }
        __syncthreads();
        const int lane = tid & 31, w = tid >> 5;
#pragma unroll
        for (int pass = 0; pass < 16; pass++) {
            int d = pass * 8 + w;
            float2 v = *(float2*)&smT[d * 66 + 2 * lane];
            uint32_t hw, mw; split_pack(v.x, v.y, hw, mw);
            size_t o = ((size_t)(b * HNUM + h) * 128 + d) * 1024 + pt * 32 + lane;
            VTH[o] = hw; VTM[o] = mw;
        }
    } else {
        const int rid = bx - 1024;
        const int tens = rid >> 11;
        const int baserow = (rid & 2047) * 2;
        const float* src = tens ? qr : kr;
        uint32_t* OH = tens ? QH : KH;
        uint32_t* OM = tens ? QM : KM;
#pragma unroll
        for (int j = 0; j < 4; j++) {
            int u = tid + j * 256;
            int row = baserow + (u >> 9);
            int w = u & 511;
            int h = w >> 5, u5 = w & 31;
            float2 v = *(const float2*)&src[(size_t)row * 1024 + h * HD2 + 2 * u5];
            int t = row & (TDIM - 1);
            int pr = h * 32 + u5;
            const float c1 = (float)(-9.210340371976184 / 1024.0);
            float fr  = expf((float)(2 * pr) * c1);
            float ang = (float)t * fr;
            double ad = (double)ang;
            double rr = ad - floor(ad * 0.15915494309189535) * 6.283185307179586;
            float s = sinf((float)rr), cc = cosf((float)rr);
            float xe = v.x, xo = v.y;
            float r0 = xe * cc - xo * s;
            float r1 = xo * cc + xe * s;
            uint32_t hw, mw; split_pack(r0, r1, hw, mw);
            OH[(size_t)row * 1024 + h * 64 + 32 + u5] = hw;
            OM[(size_t)row * 1024 + h * 64 + 32 + u5] = mw;
        }
    }
}

// ====================== bf16x3 flash attention =============================
#define AQH 0
#define AQM 4352
#define AKH 8704
#define AKM 13056
#define AVH 17408
#define AVM 19968
#define APH 22528
#define APM 23808
#define ATTN_SMEM (25088 * 4)

__global__ __launch_bounds__(128) void attn_bf3(
    const uint32_t* __restrict__ QHg, const uint32_t* __restrict__ QMg,
    const uint32_t* __restrict__ KHg, const uint32_t* __restrict__ KMg,
    const uint32_t* __restrict__ VTHg, const uint32_t* __restrict__ VTMg,
    uint32_t* __restrict__ OHg, uint32_t* __restrict__ OMg)
{
    extern __shared__ uint32_t smw[];
    const uint32_t smb = smem_u32(smw);
    const int tid = threadIdx.x, wid = tid >> 5, lane = tid & 31;
    const int g = lane >> 2, q = lane & 3;
    const int r8 = lane & 7, mq = lane >> 3;
    const int it = 31 - blockIdx.x;
    const int h = blockIdx.y, b = blockIdx.z;
    const int q0 = it * 64, rowbase = b * TDIM;
    const float scale = 0.08838834764831845f;

    uint32_t* PH = smw + APH;  uint32_t* PM = smw + APM;

    auto cpK = [&](int tk, int slot) {
#pragma unroll
        for (int j = 0; j < 8; j++) {
            int f = tid + j * 128;
            int ff = f & 511;
            int row = ff >> 4, c4 = ff & 15;
            const uint32_t* gsrc = (f < 512) ? KHg : KMg;
            uint32_t dst = smb + (((f < 512) ? AKH : AKM) + slot * 2176
                                  + row * 68 + c4 * 4) * 4;
            cp16(dst, gsrc + (size_t)(rowbase + tk + row) * 1024 + h * 64 + c4 * 4);
        }
    };
    auto cpV = [&](int tk) {
#pragma unroll
        for (int j = 0; j < 8; j++) {
            int f = tid + j * 128;
            int ff = f & 511;
            int d = ff >> 2, c4 = ff & 3;
            const uint32_t* gsrc = (f < 512) ? VTHg : VTMg;
            uint32_t dst = smb + (((f < 512) ? AVH : AVM) + d * 20 + c4 * 4) * 4;
            cp16(dst, gsrc + ((size_t)(b * HNUM + h) * 128 + d) * 1024
                        + (tk >> 1) + c4 * 4);
        }
    };

#pragma unroll
    for (int j = 0; j < 16; j++) {
        int f = tid + j * 128;
        int ff = f & 1023;
        int row = ff >> 4, c4 = ff & 15;
        const uint32_t* gsrc = (f < 1024) ? QHg : QMg;
        uint32_t dst = smb + (((f < 1024) ? AQH : AQM) + row * 68 + c4 * 4) * 4;
        cp16(dst, gsrc + (size_t)(rowbase + q0 + row) * 1024 + h * 64 + c4 * 4);
    }
    cpK(0, 0);
    CP_COMMIT();
    cpV(0);
    CP_COMMIT();

    float o[16][4];
#pragma unroll
    for (int jt = 0; jt < 16; jt++)
#pragma unroll
        for (int e = 0; e < 4; e++) o[jt][e] = 0.f;
    float m_old0 = -1e30f, m_old1 = -1e30f, l0 = 0.f, l1 = 0.f;

    const int kmax = 2 * it + 1;
    const int gr0 = q0 + 16 * wid + g, gr1 = gr0 + 8;
    const int qwr = 16 * wid;

    for (int kb = 0; kb <= kmax; kb++) {
        if (kb < kmax) cpK((kb + 1) * 32, (kb + 1) & 1);
        CP_COMMIT();
        CP_WAIT(2);
        __syncthreads();

        const bool active = (kb * 32 <= q0 + qwr + 15);
        if (active) {
            const uint32_t sKH = smb + (uint32_t)(AKH + (kb & 1) * 2176) * 4;
            const uint32_t sKM = smb + (uint32_t)(AKM + (kb & 1) * 2176) * 4;
            const uint32_t sQH = smb + AQH * 4;
            const uint32_t sQM = smb + AQM * 4;

            float sacc[4][4];
#pragma unroll
            for (int j = 0; j < 4; j++)
#pragma unroll
                for (int e = 0; e < 4; e++) sacc[j][e] = 0.f;

#pragma unroll
            for (int c = 0; c < 8; c++) {
                uint32_t Ah[4], Am[4];
                uint32_t aoff = (uint32_t)(((qwr + r8 + (mq & 1) * 8) * 68
                                            + c * 8 + (mq >> 1) * 4) * 4);
                ldsm_x4(Ah[0], Ah[1], Ah[2], Ah[3], sQH + aoff);
                ldsm_x4(Am[0], Am[1], Am[2], Am[3], sQM + aoff);
                uint32_t Bh[4][2], Bm[4][2];
#pragma unroll
                for (int u = 0; u < 2; u++) {
                    uint32_t boff = (uint32_t)((((2 * u + (mq >> 1)) * 8 + r8) * 68
                                                + c * 8 + (mq & 1) * 4) * 4);
                    ldsm_x4(Bh[2*u][0], Bh[2*u][1], Bh[2*u+1][0], Bh[2*u+1][1], sKH + boff);
                    ldsm_x4(Bm[2*u][0], Bm[2*u][1], Bm[2*u+1][0], Bm[2*u+1][1], sKM + boff);
                }
#pragma unroll
                for (int j = 0; j < 4; j++) {
                    mma_bf16(sacc[j], Ah, Bh[j]);
                    mma_bf16(sacc[j], Ah, Bm[j]);
                    mma_bf16(sacc[j], Am, Bh[j]);
                }
            }

            float mx0 = -1e30f, mx1 = -1e30f;
#pragma unroll
            for (int j = 0; j < 4; j++) {
                int colb = kb * 32 + j * 8 + 2 * q;
                float v0 = sacc[j][0] * scale; if (colb     > gr0) v0 = -1e30f;
                float v1 = sacc[j][1] * scale; if (colb + 1 > gr0) v1 = -1e30f;
                float v2 = sacc[j][2] * scale; if (colb     > gr1) v2 = -1e30f;
                float v3 = sacc[j][3] * scale; if (colb + 1 > gr1) v3 = -1e30f;
                sacc[j][0] = v0; sacc[j][1] = v1; sacc[j][2] = v2; sacc[j][3] = v3;
                mx0 = fmaxf(mx0, fmaxf(v0, v1));
                mx1 = fmaxf(mx1, fmaxf(v2, v3));
            }
            mx0 = fmaxf(mx0, __shfl_xor_sync(0xffffffffu, mx0, 1));
            mx0 = fmaxf(mx0, __shfl_xor_sync(0xffffffffu, mx0, 2));
            mx1 = fmaxf(mx1, __shfl_xor_sync(0xffffffffu, mx1, 1));
            mx1 = fmaxf(mx1, __shfl_xor_sync(0xffffffffu, mx1, 2));

            float mn0 = fmaxf(m_old0, mx0), mn1 = fmaxf(m_old1, mx1);
            float al0 = fexp(m_old0 - mn0), al1 = fexp(m_old1 - mn1);
            float ps0 = 0.f, ps1 = 0.f;
#pragma unroll
            for (int j = 0; j < 4; j++) {
                float p0 = fexp(sacc[j][0] - mn0);
                float p1 = fexp(sacc[j][1] - mn0);
                float p2 = fexp(sacc[j][2] - mn1);
                float p3 = fexp(sacc[j][3] - mn1);
                ps0 += p0 + p1; ps1 += p2 + p3;
                uint32_t hw, mw;
                split_pack(p0, p1, hw, mw);
                PH[(qwr + g) * 20 + j * 4 + q] = hw;
                PM[(qwr + g) * 20 + j * 4 + q] = mw;
                split_pack(p2, p3, hw, mw);
                PH[(qwr + g + 8) * 20 + j * 4 + q] = hw;
                PM[(qwr + g + 8) * 20 + j * 4 + q] = mw;
            }
            ps0 += __shfl_xor_sync(0xffffffffu, ps0, 1);
            ps0 += __shfl_xor_sync(0xffffffffu, ps0, 2);
            ps1 += __shfl_xor_sync(0xffffffffu, ps1, 1);
            ps1 += __shfl_xor_sync(0xffffffffu, ps1, 2);
            l0 = l0 * al0 + ps0; l1 = l1 * al1 + ps1;
            m_old0 = mn0; m_old1 = mn1;
#pragma unroll
            for (int jt = 0; jt < 16; jt++) {
                o[jt][0] *= al0; o[jt][1] *= al0;
                o[jt][2] *= al1; o[jt][3] *= al1;
            }
        }

        CP_WAIT(1);
        __syncthreads();

        if (active) {
            __syncwarp();
            const uint32_t sPH = smb + APH * 4;
            const uint32_t sPM = smb + APM * 4;
            const uint32_t sVH = smb + AVH * 4;
            const uint32_t sVM = smb + AVM * 4;
#pragma unroll
            for (int c = 0; c < 2; c++) {
                uint32_t Ah[4], Am[4];
                uint32_t aoff = (uint32_t)(((qwr + r8 + (mq & 1) * 8) * 20
                                            + c * 8 + (mq >> 1) * 4) * 4);
                ldsm_x4(Ah[0], Ah[1], Ah[2], Ah[3], sPH + aoff);
                ldsm_x4(Am[0], Am[1], Am[2], Am[3], sPM + aoff);
#pragma unroll
                for (int u = 0; u < 8; u++) {
                    uint32_t Bh[2][2], Bm[2][2];
                    uint32_t boff = (uint32_t)((((2 * u + (mq >> 1)) * 8 + r8) * 20
                                                + c * 8 + (mq & 1) * 4) * 4);
                    ldsm_x4(Bh[0][0], Bh[0][1], Bh[1][0], Bh[1][1], sVH + boff);
                    ldsm_x4(Bm[0][0], Bm[0][1], Bm[1][0], Bm[1][1], sVM + boff);
#pragma unroll
                    for (int t2 = 0; t2 < 2; t2++) {
                        int jt = 2 * u + t2;
                        mma_bf16(o[jt], Ah, Bh[t2]);
                        mma_bf16(o[jt], Ah, Bm[t2]);
                        mma_bf16(o[jt], Am, Bh[t2]);
                    }
                }
            }
        }

        __syncthreads();
        if (kb < kmax) cpV((kb + 1) * 32);
        CP_COMMIT();
    }

    float inv0 = 1.f / l0, inv1 = 1.f / l1;
    size_t ob0 = (size_t)(rowbase + gr0) * 1024 + h * 64;
    size_t ob1 = (size_t)(rowbase + gr1) * 1024 + h * 64;
#pragma unroll
    for (int jt = 0; jt < 16; jt++) {
        uint32_t hw, mw;
        split_pack(o[jt][0] * inv0, o[jt][1] * inv0, hw, mw);
        OHg[ob0 + jt * 4 + q] = hw;
        OMg[ob0 + jt * 4 + q] = mw;
        split_pack(o[jt][2] * inv1, o[jt][3] * inv1, hw, mw);
        OHg[ob1 + jt * 4 + q] = hw;
        OMg[ob1 + jt * 4 + q] = mw;
    }
}

// ------------------------------- launch ------------------------------------
extern "C" void kernel_launch(void* const* d_in, const int* in_sizes, int n_in,
                              void* d_out, int out_size)
{
    (void)in_sizes; (void)n_in; (void)out_size;
    const float* x    = (const float*)d_in[0];
    const float* WkvD = (const float*)d_in[1];
    const float* WqD  = (const float*)d_in[2];
    const float* WkU  = (const float*)d_in[3];
    const float* WvU  = (const float*)d_in[4];
    const float* WqU  = (const float*)d_in[5];
    const float* Wrk  = (const float*)d_in[6];
    const float* Wrq  = (const float*)d_in[7];
    const float* Wo   = (const float*)d_in[8];
    float* out = (float*)d_out;

    float *kr, *qr, *vl;
    uint32_t *XH, *XM, *WkvDH, *WkvDM, *WqDH, *WqDM, *WkUH, *WkUM;
    uint32_t *WvUH, *WvUM, *WqUH, *WqUM, *WrkH, *WrkM, *WrqH, *WrqM;
    uint32_t *WoH, *WoM, *kvdH, *kvdM, *qdH, *qdM;
    uint32_t *QH, *QM, *KH, *KM, *VTH, *VTM, *attnH, *attnM;
    cudaGetSymbolAddress((void**)&kr,   g_kr);
    cudaGetSymbolAddress((void**)&qr,   g_qr);
    cudaGetSymbolAddress((void**)&vl,   g_vl);
    cudaGetSymbolAddress((void**)&XH,   g_XH);    cudaGetSymbolAddress((void**)&XM,   g_XM);
    cudaGetSymbolAddress((void**)&WkvDH,g_WkvDH); cudaGetSymbolAddress((void**)&WkvDM,g_WkvDM);
    cudaGetSymbolAddress((void**)&WqDH, g_WqDH);  cudaGetSymbolAddress((void**)&WqDM, g_WqDM);
    cudaGetSymbolAddress((void**)&WkUH, g_WkUH);  cudaGetSymbolAddress((void**)&WkUM, g_WkUM);
    cudaGetSymbolAddress((void**)&WvUH, g_WvUH);  cudaGetSymbolAddress((void**)&WvUM, g_WvUM);
    cudaGetSymbolAddress((void**)&WqUH, g_WqUH);  cudaGetSymbolAddress((void**)&WqUM, g_WqUM);
    cudaGetSymbolAddress((void**)&WrkH, g_WrkH);  cudaGetSymbolAddress((void**)&WrkM, g_WrkM);
    cudaGetSymbolAddress((void**)&WrqH, g_WrqH);  cudaGetSymbolAddress((void**)&WrqM, g_WrqM);
    cudaGetSymbolAddress((void**)&WoH,  g_WoH);   cudaGetSymbolAddress((void**)&WoM,  g_WoM);
    cudaGetSymbolAddress((void**)&kvdH, g_kvdH);  cudaGetSymbolAddress((void**)&kvdM, g_kvdM);
    cudaGetSymbolAddress((void**)&qdH,  g_qdH);   cudaGetSymbolAddress((void**)&qdM,  g_qdM);
    cudaGetSymbolAddress((void**)&QH,   g_QH);    cudaGetSymbolAddress((void**)&QM,   g_QM);
    cudaGetSymbolAddress((void**)&KH,   g_KH);    cudaGetSymbolAddress((void**)&KM,   g_KM);
    cudaGetSymbolAddress((void**)&VTH,  g_VTH);   cudaGetSymbolAddress((void**)&VTM,  g_VTM);
    cudaGetSymbolAddress((void**)&attnH,g_attnH); cudaGetSymbolAddress((void**)&attnM,g_attnM);

    cudaFuncSetAttribute(gemm_bf3, cudaFuncAttributeMaxDynamicSharedMemorySize,
                         GEMM_SMEM);
    cudaFuncSetAttribute(attn_bf3, cudaFuncAttributeMaxDynamicSharedMemorySize,
                         ATTN_SMEM);

    // L1: split x
    {
        SJobs jb{};
        jb.src[0] = x; jb.dh[0] = XH; jb.dm[0] = XM;
        for (int i = 0; i < 5; i++) jb.end[i] = 8192;
        split_w<<<8192, 256>>>(jb);
    }
    // L2: split up-weights
    {
        SJobs jb{};
        jb.src[0] = WkvD; jb.dh[0] = WkvDH; jb.dm[0] = WkvDM;
        jb.src[1] = WqD;  jb.dh[1] = WqDH;  jb.dm[1] = WqDM;
        jb.src[2] = WkU;  jb.dh[2] = WkUH;  jb.dm[2] = WkUM;
        jb.src[3] = WvU;  jb.dh[3] = WvUH;  jb.dm[3] = WvUM;
        jb.src[4] = WqU;  jb.dh[4] = WqUH;  jb.dm[4] = WqUM;
        int cnt[5] = {1024, 1024, 512, 1024, 512};
        int e = 0;
        for (int i = 0; i < 5; i++) { e += cnt[i]; jb.end[i] = e; }
        split_w<<<e, 256>>>(jb);
    }
    // L3: split big weights
    {
        SJobs jb{};
        jb.src[0] = Wrk; jb.dh[0] = WrkH; jb.dm[0] = WrkM;
        jb.src[1] = Wrq; jb.dh[1] = WrqH; jb.dm[1] = WrqM;
        jb.src[2] = Wo;  jb.dh[2] = WoH;  jb.dm[2] = WoM;
        int cnt[3] = {2048, 512, 4096};
        int e = 0;
        for (int i = 0; i < 3; i++) { e += cnt[i]; jb.end[i] = e; }
        jb.end[3] = e; jb.end[4] = e;
        split_w<<<e, 256>>>(jb);
    }
    // L4 (ncu-captured): x -> {kvd, qd, kr}   Kw=1024
    {
        GBatch gb;
        gb.s[0] = { XH, XM, WkvDH, WkvDM, nullptr, kvdH, kvdM, 0, 256, OM_SPLIT, 4 };
        gb.s[1] = { XH, XM, WqDH,  WqDM,  nullptr, qdH,  qdM,  0, 256, OM_SPLIT, 8 };
        gb.s[2] = { XH, XM, WrkH,  WrkM,  kr, nullptr, nullptr, 1024, 0, OM_F32, 16 };
        gb.s[3] = gb.s[2];
        gemm_bf3<<<dim3(16, 32), 256, GEMM_SMEM>>>(gb, 1024);
    }
    // L5: {kvd,qd} -> {kc->K, qc->Q, vl, qr}  Kw=256
    {
        GBatch gb;
        gb.s[0] = { kvdH, kvdM, WkUH, WkUM, nullptr, KH, KM, 0, 1024, OM_QKMAP, 8 };
        gb.s[1] = { qdH,  qdM,  WqUH, WqUM, nullptr, QH, QM, 0, 1024, OM_QKMAP, 16 };
        gb.s[2] = { kvdH, kvdM, WvUH, WvUM, vl, nullptr, nullptr, 2048, 0, OM_F32, 32 };
        gb.s[3] = { qdH,  qdM,  WrqH, WrqM, qr, nullptr, nullptr, 1024, 0, OM_F32, 40 };
        gemm_bf3<<<dim3(40, 32), 256, GEMM_SMEM>>>(gb, 256);
    }
    // L6: V transpose+split, rope+split
    split_vr<<<5120, 256>>>(vl, kr, qr, VTH, VTM, QH, QM, KH, KM);
    // L7: attention
    attn_bf3<<<dim3(32, HNUM, 2), 128, ATTN_SMEM>>>(
        QH, QM, KH, KM, VTH, VTM, attnH, attnM);
    // L8: output projection  Kw=1024
    {
        GBatch gb;
        gb.s[0] = { attnH, attnM, WoH, WoM, out, nullptr, nullptr, 2048, 0, OM_F32, 16 };
        gb.s[1] = gb.s[0]; gb.s[2] = gb.s[0]; gb.s[3] = gb.s[0];
        gemm_bf3<<<dim3(16, 32), 256, GEMM_SMEM>>>(gb, 1024);
    }
}